// round 5
// baseline (speedup 1.0000x reference)
#include <cuda_runtime.h>
#include <math.h>

// Problem constants
#define NPATHS 8192
#define SEQ    512
#define NSTEP  511
#define HID    128
#define PB     64          // paths per block
#define NTHR   256
#define NBLK   (NPATHS / PB)   // 128

#define MIN_VOL 1e-4f
#define MAX_VOL 5.0f

// ---- shared memory layout (in floats) ----
#define S_FW1 0            // 3*128
#define S_FB1 384          // 128
#define S_FW2 512          // 128*128
#define S_FB2 16896        // 128
#define S_FW3 17024        // 128*2
#define S_FB3 17280        // 2 (pad to 4)
#define S_GW1 17284        // 2*128
#define S_GB1 17540        // 128
#define S_GW2 17668        // 128*128
#define S_GB2 34052        // 128
#define S_GW3 34180        // 128*2
#define S_GB3 34436        // 2 (pad to 4)
#define S_TS  34440        // 512
#define S_A   34952        // 128*64 activation buffer (layout [hidden][path])
#define S_B   43144        // 128*64 activation buffer
#define S_YSH 51336        // 64*2 current state
#define S_FV  51464        // 64*2 drift
#define S_RAW 51592        // 64*2 diffusion pre-activation
#define S_GV  51720        // 64*2 clipped diffusion
#define S_DWV 51848        // 64*2 brownian increment
#define S_DRW 51976        // 64*2 delta_raw
#define S_COR 52104        // 64*2 Milstein correction
#define S_TOT 52232
#define SMEM_BYTES (S_TOT * 4)

// ---- packed f32x2 helpers (sm_103a) ----
__device__ __forceinline__ void ffma2(unsigned long long& d, unsigned long long a, unsigned long long b) {
    asm("fma.rn.f32x2 %0, %1, %2, %0;" : "+l"(d) : "l"(a), "l"(b));
}
__device__ __forceinline__ unsigned long long dup2(float w) {
    unsigned long long r;
    asm("mov.b64 %0, {%1, %1};" : "=l"(r) : "f"(w));
    return r;
}
__device__ __forceinline__ float2 upk(unsigned long long u) {
    float2 v;
    asm("mov.b64 {%0, %1}, %2;" : "=f"(v.x), "=f"(v.y) : "l"(u));
    return v;
}

__device__ __forceinline__ float sigm(float z) {
    return __fdividef(1.0f, 1.0f + __expf(-z));
}
__device__ __forceinline__ float silu_(float z) {
    return z * sigm(z);
}
__device__ __forceinline__ float dsilu(float z) {
    float s = sigm(z);
    return s * (1.0f + z * (1.0f - s));
}

// 64x128 GEMM mainloop: out[p][j] = sum_k A[k][p] * W(k,j)
// A layout: [k][p] i.e. A[k*64+p].  TRANS=false: W(k,j)=W[k*128+j]; TRANS=true: W(k,j)=W[j*128+k]
// thread tile: 4 paths (pg*4..+3, as 2 f32x2 pairs) x 8 cols (cg*8..+7)
template <bool TRANS>
__device__ __forceinline__ void gemm_core(const float* __restrict__ sA,
                                          const float* __restrict__ sW,
                                          int pg, int cg, unsigned long long acc[16]) {
    const float* ab = sA + pg * 4;
#pragma unroll 4
    for (int k = 0; k < HID; ++k) {
        unsigned long long h0 = *(const unsigned long long*)(ab + k * PB);
        unsigned long long h1 = *(const unsigned long long*)(ab + k * PB + 2);
        float w[8];
        if (!TRANS) {
            float4 wa = *(const float4*)(sW + k * HID + cg * 8);
            float4 wb = *(const float4*)(sW + k * HID + cg * 8 + 4);
            w[0] = wa.x; w[1] = wa.y; w[2] = wa.z; w[3] = wa.w;
            w[4] = wb.x; w[5] = wb.y; w[6] = wb.z; w[7] = wb.w;
        } else {
#pragma unroll
            for (int c = 0; c < 8; ++c) w[c] = sW[(cg * 8 + c) * HID + k];
        }
#pragma unroll
        for (int c = 0; c < 8; ++c) {
            unsigned long long wd = dup2(w[c]);
            ffma2(acc[2 * c], h0, wd);
            ffma2(acc[2 * c + 1], h1, wd);
        }
    }
}

__global__ void __launch_bounds__(NTHR, 1) sde_kernel(
    const float* __restrict__ y0, const float* __restrict__ ts, const float* __restrict__ dW,
    const float* __restrict__ fw1, const float* __restrict__ fb1,
    const float* __restrict__ fw2, const float* __restrict__ fb2,
    const float* __restrict__ fw3, const float* __restrict__ fb3,
    const float* __restrict__ gw1, const float* __restrict__ gb1,
    const float* __restrict__ gw2, const float* __restrict__ gb2,
    const float* __restrict__ gw3, const float* __restrict__ gb3,
    float* __restrict__ out) {
    extern __shared__ float sm[];
    const int tid = threadIdx.x;
    const int p0 = blockIdx.x * PB;

    // cooperative weight load
    {
        auto cp = [&](int dst, const float* src, int n) {
            for (int i = tid; i < n; i += NTHR) sm[dst + i] = src[i];
        };
        cp(S_FW1, fw1, 384);  cp(S_FB1, fb1, 128);
        cp(S_FW2, fw2, 16384); cp(S_FB2, fb2, 128);
        cp(S_FW3, fw3, 256);  cp(S_FB3, fb3, 2);
        cp(S_GW1, gw1, 256);  cp(S_GB1, gb1, 128);
        cp(S_GW2, gw2, 16384); cp(S_GB2, gb2, 128);
        cp(S_GW3, gw3, 256);  cp(S_GB3, gb3, 2);
        cp(S_TS, ts, SEQ);
    }
    // init state + write t=0 output
    if (tid < PB * 2) {
        float v = y0[p0 * 2 + tid];
        sm[S_YSH + tid] = v;
        out[(size_t)(p0 + (tid >> 1)) * (SEQ * 2) + (tid & 1)] = v;
    }
    __syncthreads();

    const int pg = tid & 15;   // path group (4 paths)
    const int cg = tid >> 4;   // col group (8 cols)

    for (int t = 0; t < NSTEP; ++t) {
        // prefetch this step's dW slice (consumed in pass 7)
        float dwraw = 0.0f;
        if (tid < PB * 2) dwraw = dW[(size_t)t * (NPATHS * 2) + p0 * 2 + tid];
        const float dt = sm[S_TS + t + 1] - sm[S_TS + t];
        const float sqdt = sqrtf(dt);

        // pass 1: H1 = silu([y, spread] @ fw1 + fb1) -> A
        for (int e = tid; e < HID * PB; e += NTHR) {
            int j = e >> 6, p = e & 63;
            float a = sm[S_YSH + p * 2], b = sm[S_YSH + p * 2 + 1];
            float z = sm[S_FB1 + j] + a * sm[S_FW1 + j] + b * sm[S_FW1 + 128 + j]
                      + (a - b) * sm[S_FW1 + 256 + j];
            sm[S_A + e] = silu_(z);
        }
        __syncthreads();

        // GEMM: H2 = silu(H1 @ fw2 + fb2) -> B
        {
            unsigned long long acc[16] = {};
            gemm_core<false>(sm + S_A, sm + S_FW2, pg, cg, acc);
#pragma unroll
            for (int c = 0; c < 8; ++c) {
                int j = cg * 8 + c;
                float bb = sm[S_FB2 + j];
                float2 v0 = upk(acc[2 * c]), v1 = upk(acc[2 * c + 1]);
                float4 o;
                o.x = silu_(v0.x + bb); o.y = silu_(v0.y + bb);
                o.z = silu_(v1.x + bb); o.w = silu_(v1.y + bb);
                *(float4*)(sm + S_B + j * PB + pg * 4) = o;
            }
        }
        __syncthreads();

        // pass 3: f = H2 @ fw3 + fb3  (2 threads per output, shfl combine)
        {
            int o = tid >> 1, half = tid & 1;
            int p = o >> 1, c = o & 1;
            int jb = half * 64;
            float s = 0.0f;
            for (int j = 0; j < 64; ++j)
                s += sm[S_B + (jb + j) * PB + p] * sm[S_FW3 + (jb + j) * 2 + c];
            s += __shfl_xor_sync(0xffffffffu, s, 1);
            if (half == 0) sm[S_FV + o] = s + sm[S_FB3 + c];
        }
        // pass 4: G1 = silu(y @ gw1 + gb1) -> A  (A dead after fw2 GEMM)
        for (int e = tid; e < HID * PB; e += NTHR) {
            int j = e >> 6, p = e & 63;
            float z = sm[S_GB1 + j] + sm[S_YSH + p * 2] * sm[S_GW1 + j]
                      + sm[S_YSH + p * 2 + 1] * sm[S_GW1 + 128 + j];
            sm[S_A + e] = silu_(z);
        }
        __syncthreads();

        // GEMM: Z2g = G1 @ gw2 + gb2 (pre-activation) -> B
        {
            unsigned long long acc[16] = {};
            gemm_core<false>(sm + S_A, sm + S_GW2, pg, cg, acc);
#pragma unroll
            for (int c = 0; c < 8; ++c) {
                int j = cg * 8 + c;
                float bb = sm[S_GB2 + j];
                float2 v0 = upk(acc[2 * c]), v1 = upk(acc[2 * c + 1]);
                float4 o;
                o.x = v0.x + bb; o.y = v0.y + bb; o.z = v1.x + bb; o.w = v1.y + bb;
                *(float4*)(sm + S_B + j * PB + pg * 4) = o;
            }
        }
        __syncthreads();

        // pass 6a: G2 = silu(Z2g) -> A
        for (int e = tid; e < HID * PB; e += NTHR) sm[S_A + e] = silu_(sm[S_B + e]);
        __syncthreads();

        // pass 6b: raw = G2 @ gw3 + gb3
        {
            int o = tid >> 1, half = tid & 1;
            int p = o >> 1, c = o & 1;
            int jb = half * 64;
            float s = 0.0f;
            for (int j = 0; j < 64; ++j)
                s += sm[S_A + (jb + j) * PB + p] * sm[S_GW3 + (jb + j) * 2 + c];
            s += __shfl_xor_sync(0xffffffffu, s, 1);
            if (half == 0) sm[S_RAW + o] = s + sm[S_GB3 + c];
        }
        __syncthreads();

        // pass 7: per-path scalars: g = clip(softplus(raw)), delta_raw = v*g*sigma(raw)*mask
        if (tid < PB * 2) {
            float dw = dwraw * sqdt;
            float raw = sm[S_RAW + tid];
            float sp = fmaxf(raw, 0.0f) + log1pf(__expf(-fabsf(raw)));
            float g = fminf(fmaxf(sp, MIN_VOL), MAX_VOL);
            float mask = (sp > MIN_VOL && sp < MAX_VOL) ? 1.0f : 0.0f;
            float v = 0.5f * (dw * dw - dt);
            sm[S_DRW + tid] = v * g * sigm(raw) * mask;
            sm[S_GV + tid] = g;
            sm[S_DWV + tid] = dw;
        }
        __syncthreads();

        // pass 8: delta_Z2g = silu'(Z2g) * (delta_raw @ gw3^T)  (in-place on B)
        for (int e = tid; e < HID * PB; e += NTHR) {
            int j = e >> 6, p = e & 63;
            float z = sm[S_B + e];
            float u = sm[S_DRW + p * 2] * sm[S_GW3 + j * 2]
                      + sm[S_DRW + p * 2 + 1] * sm[S_GW3 + j * 2 + 1];
            sm[S_B + e] = dsilu(z) * u;
        }
        __syncthreads();

        // GEMM back: delta_Z1g = (delta_Z2g @ gw2^T) * silu'(z1g recomputed) -> A
        {
            unsigned long long acc[16] = {};
            gemm_core<true>(sm + S_B, sm + S_GW2, pg, cg, acc);
#pragma unroll
            for (int c = 0; c < 8; ++c) {
                int i = cg * 8 + c;
                float w0 = sm[S_GW1 + i], w1 = sm[S_GW1 + 128 + i], bb = sm[S_GB1 + i];
                float2 v0 = upk(acc[2 * c]), v1 = upk(acc[2 * c + 1]);
                float vv[4] = {v0.x, v0.y, v1.x, v1.y};
                float4 o;
                float* op = &o.x;
#pragma unroll
                for (int q = 0; q < 4; ++q) {
                    int p = pg * 4 + q;
                    float z1 = sm[S_YSH + p * 2] * w0 + sm[S_YSH + p * 2 + 1] * w1 + bb;
                    op[q] = vv[q] * dsilu(z1);
                }
                *(float4*)(sm + S_A + i * PB + pg * 4) = o;
            }
        }
        __syncthreads();

        // pass 10: corr = delta_Z1g @ gw1^T
        {
            int o = tid >> 1, half = tid & 1;
            int p = o >> 1, c = o & 1;
            int ib = half * 64;
            float s = 0.0f;
            for (int i = 0; i < 64; ++i)
                s += sm[S_A + (ib + i) * PB + p] * sm[S_GW1 + c * 128 + ib + i];
            s += __shfl_xor_sync(0xffffffffu, s, 1);
            if (half == 0) sm[S_COR + o] = s;
        }
        __syncthreads();

        // pass 11: y <- y + f*dt + g*dw + corr, write output
        if (tid < PB * 2) {
            float y1 = sm[S_YSH + tid] + sm[S_FV + tid] * dt
                       + sm[S_GV + tid] * sm[S_DWV + tid] + sm[S_COR + tid];
            sm[S_YSH + tid] = y1;
            out[(size_t)(p0 + (tid >> 1)) * (SEQ * 2) + (size_t)(t + 1) * 2 + (tid & 1)] = y1;
        }
        __syncthreads();
    }
}

extern "C" void kernel_launch(void* const* d_in, const int* in_sizes, int n_in,
                              void* d_out, int out_size) {
    (void)in_sizes; (void)n_in; (void)out_size;
    cudaFuncSetAttribute(sde_kernel, cudaFuncAttributeMaxDynamicSharedMemorySize, SMEM_BYTES);
    sde_kernel<<<NBLK, NTHR, SMEM_BYTES>>>(
        (const float*)d_in[0], (const float*)d_in[1], (const float*)d_in[2],
        (const float*)d_in[3], (const float*)d_in[4], (const float*)d_in[5],
        (const float*)d_in[6], (const float*)d_in[7], (const float*)d_in[8],
        (const float*)d_in[9], (const float*)d_in[10], (const float*)d_in[11],
        (const float*)d_in[12], (const float*)d_in[13], (const float*)d_in[14],
        (float*)d_out);
}

// round 6
// speedup vs baseline: 1.1140x; 1.1140x over previous
#include <cuda_runtime.h>
#include <math.h>

#define NPATHS 8192
#define SEQ    512
#define NSTEP  511
#define HID    128
#define PB     64
#define NTHR   512
#define NBLK   (NPATHS / PB)

#define MIN_VOL 1e-4f
#define MAX_VOL 5.0f

#define GWS 132   // padded row stride for gw2 (conflict-free transposed reads)

// ---- shared memory layout (floats) ----
#define S_FW1 0
#define S_FB1 384
#define S_FW2 512
#define S_FB2 16896
#define S_FW3 17024
#define S_FB3 17280
#define S_GW1 17284
#define S_GB1 17540
#define S_GW2 17668          // 132*128 = 16896
#define S_GB2 34564
#define S_GW3 34692
#define S_GB3 34948
#define S_TS  34952
#define S_A   35464          // 128*64
#define S_B   43656          // 128*64
#define S_YSH 51848
#define S_FV  51976
#define S_GV  52104
#define S_DWV 52232
#define S_DRW 52360
#define S_TOT 52488
#define SMEM_BYTES (S_TOT * 4)

// ---- packed f32x2 helpers ----
__device__ __forceinline__ void ffma2(unsigned long long& d, unsigned long long a, unsigned long long b) {
    asm("fma.rn.f32x2 %0, %1, %2, %0;" : "+l"(d) : "l"(a), "l"(b));
}
__device__ __forceinline__ unsigned long long dup2(float w) {
    unsigned long long r;
    asm("mov.b64 %0, {%1, %1};" : "=l"(r) : "f"(w));
    return r;
}
__device__ __forceinline__ float2 upk(unsigned long long u) {
    float2 v;
    asm("mov.b64 {%0, %1}, %2;" : "=f"(v.x), "=f"(v.y) : "l"(u));
    return v;
}

// exp-based sigmoid (accurate; forward path)
__device__ __forceinline__ float sigm(float z) {
    return __fdividef(1.0f, 1.0f + __expf(-z));
}
__device__ __forceinline__ float silu_(float z) { return z * sigm(z); }

// tanh-based sigmoid (1 MUFU; used only in Milstein-correction dsilu factors)
__device__ __forceinline__ float sigm_t(float z) {
    float th;
    asm("tanh.approx.f32 %0, %1;" : "=f"(th) : "f"(0.5f * z));
    return 0.5f * th + 0.5f;
}
__device__ __forceinline__ float dsilu_t(float z) {
    float s = sigm_t(z);
    return s * (1.0f + z * (1.0f - s));
}

// forward GEMM mainloop: acc[p][j] += sum_k A[k][p] * W[k][j]
// thread tile: 4 paths (pg*4..+3 as 2 u64 pairs) x 4 cols (cg*4..+3)
__device__ __forceinline__ void gemm_fwd(const float* __restrict__ sA,
                                         const float* __restrict__ sW, int ws,
                                         int pg, int cg, unsigned long long acc[8]) {
#pragma unroll 2
    for (int k4 = 0; k4 < HID; k4 += 4) {
        ulonglong2 h[4];
#pragma unroll
        for (int u = 0; u < 4; ++u)
            h[u] = *(const ulonglong2*)(sA + (k4 + u) * PB + pg * 4);
#pragma unroll
        for (int u = 0; u < 4; ++u) {
            float4 w = *(const float4*)(sW + (k4 + u) * ws + cg * 4);
            unsigned long long w0 = dup2(w.x), w1 = dup2(w.y), w2 = dup2(w.z), w3 = dup2(w.w);
            ffma2(acc[0], h[u].x, w0); ffma2(acc[1], h[u].y, w0);
            ffma2(acc[2], h[u].x, w1); ffma2(acc[3], h[u].y, w1);
            ffma2(acc[4], h[u].x, w2); ffma2(acc[5], h[u].y, w2);
            ffma2(acc[6], h[u].x, w3); ffma2(acc[7], h[u].y, w3);
        }
    }
}

// backward GEMM mainloop: acc[p][i] += sum_k B[k][p] * W[i][k]  (W rows contiguous, stride GWS)
__device__ __forceinline__ void gemm_bwd(const float* __restrict__ sB,
                                         const float* __restrict__ sW,
                                         int pg, int cg, unsigned long long acc[8]) {
#pragma unroll 2
    for (int k4 = 0; k4 < HID; k4 += 4) {
        ulonglong2 h[4];
#pragma unroll
        for (int u = 0; u < 4; ++u)
            h[u] = *(const ulonglong2*)(sB + (k4 + u) * PB + pg * 4);
#pragma unroll
        for (int c = 0; c < 4; ++c) {
            float4 w = *(const float4*)(sW + (cg * 4 + c) * GWS + k4);
            unsigned long long wd;
            wd = dup2(w.x); ffma2(acc[2 * c], h[0].x, wd); ffma2(acc[2 * c + 1], h[0].y, wd);
            wd = dup2(w.y); ffma2(acc[2 * c], h[1].x, wd); ffma2(acc[2 * c + 1], h[1].y, wd);
            wd = dup2(w.z); ffma2(acc[2 * c], h[2].x, wd); ffma2(acc[2 * c + 1], h[2].y, wd);
            wd = dup2(w.w); ffma2(acc[2 * c], h[3].x, wd); ffma2(acc[2 * c + 1], h[3].y, wd);
        }
    }
}

__global__ void __launch_bounds__(NTHR, 1) sde_kernel(
    const float* __restrict__ y0, const float* __restrict__ ts, const float* __restrict__ dW,
    const float* __restrict__ fw1, const float* __restrict__ fb1,
    const float* __restrict__ fw2, const float* __restrict__ fb2,
    const float* __restrict__ fw3, const float* __restrict__ fb3,
    const float* __restrict__ gw1, const float* __restrict__ gb1,
    const float* __restrict__ gw2, const float* __restrict__ gb2,
    const float* __restrict__ gw3, const float* __restrict__ gb3,
    float* __restrict__ out) {
    extern __shared__ float sm[];
    const int tid = threadIdx.x;
    const int p0 = blockIdx.x * PB;

    // cooperative weight load (gw2 padded to stride GWS)
    {
        auto cp = [&](int dst, const float* src, int n) {
            for (int i = tid; i < n; i += NTHR) sm[dst + i] = src[i];
        };
        cp(S_FW1, fw1, 384);   cp(S_FB1, fb1, 128);
        cp(S_FW2, fw2, 16384); cp(S_FB2, fb2, 128);
        cp(S_FW3, fw3, 256);   cp(S_FB3, fb3, 2);
        cp(S_GW1, gw1, 256);   cp(S_GB1, gb1, 128);
        cp(S_GB2, gb2, 128);
        cp(S_GW3, gw3, 256);   cp(S_GB3, gb3, 2);
        cp(S_TS, ts, SEQ);
        for (int i = tid; i < 16384; i += NTHR)
            sm[S_GW2 + (i >> 7) * GWS + (i & 127)] = gw2[i];
    }
    if (tid < PB * 2) {
        float v = y0[p0 * 2 + tid];
        sm[S_YSH + tid] = v;
        out[(size_t)(p0 + (tid >> 1)) * (SEQ * 2) + (tid & 1)] = v;
    }
    __syncthreads();

    const int pg = tid & 15;   // 16 path groups x 4 paths
    const int cg = tid >> 4;   // 32 col groups x 4 cols

    for (int t = 0; t < NSTEP; ++t) {
        const float dt = sm[S_TS + t + 1] - sm[S_TS + t];
        const float sqdt = sqrtf(dt);

        // dW prefetch (scaled) into S_DWV + pass 1: H1 = silu([y,spread]@fw1+fb1) -> A
        if (tid < PB * 2)
            sm[S_DWV + tid] = dW[(size_t)t * (NPATHS * 2) + p0 * 2 + tid] * sqdt;
#pragma unroll
        for (int it = 0; it < 4; ++it) {
            int i4 = tid + it * NTHR;          // float4 index over 2048
            int j = i4 >> 4, pb = (i4 & 15) * 4;
            float4 y01 = *(const float4*)(sm + S_YSH + pb * 2);
            float4 y23 = *(const float4*)(sm + S_YSH + pb * 2 + 4);
            float wa = sm[S_FW1 + j], wb = sm[S_FW1 + 128 + j], ws = sm[S_FW1 + 256 + j];
            float bb = sm[S_FB1 + j];
            float4 o;
            o.x = silu_(bb + y01.x * wa + y01.y * wb + (y01.x - y01.y) * ws);
            o.y = silu_(bb + y01.z * wa + y01.w * wb + (y01.z - y01.w) * ws);
            o.z = silu_(bb + y23.x * wa + y23.y * wb + (y23.x - y23.y) * ws);
            o.w = silu_(bb + y23.z * wa + y23.w * wb + (y23.z - y23.w) * ws);
            *(float4*)(sm + S_A + j * PB + pb) = o;
        }
        __syncthreads();

        // GEMM 2: H2 = silu(H1 @ fw2 + fb2) -> B
        {
            unsigned long long acc[8] = {};
            gemm_fwd(sm + S_A, sm + S_FW2, HID, pg, cg, acc);
#pragma unroll
            for (int c = 0; c < 4; ++c) {
                int j = cg * 4 + c;
                float bb = sm[S_FB2 + j];
                float2 a = upk(acc[2 * c]), b = upk(acc[2 * c + 1]);
                float4 o;
                o.x = silu_(a.x + bb); o.y = silu_(a.y + bb);
                o.z = silu_(b.x + bb); o.w = silu_(b.y + bb);
                *(float4*)(sm + S_B + j * PB + pg * 4) = o;
            }
        }
        __syncthreads();

        // pass 3 (tid<128): f = H2 @ fw3 + fb3   |   pass 4 (tid>=128): G1 = silu(y@gw1+gb1) -> A
        if (tid < 128) {
            int p = tid >> 1, d = tid & 1;
            float s0 = 0.0f, s1 = 0.0f;
#pragma unroll 4
            for (int j = 0; j < HID; j += 2) {
                s0 += sm[S_B + j * PB + p] * sm[S_FW3 + j * 2 + d];
                s1 += sm[S_B + (j + 1) * PB + p] * sm[S_FW3 + (j + 1) * 2 + d];
            }
            sm[S_FV + tid] = s0 + s1 + sm[S_FB3 + d];
        } else {
            for (int i4 = tid - 128; i4 < 2048; i4 += NTHR - 128) {
                int j = i4 >> 4, pb = (i4 & 15) * 4;
                float4 y01 = *(const float4*)(sm + S_YSH + pb * 2);
                float4 y23 = *(const float4*)(sm + S_YSH + pb * 2 + 4);
                float wa = sm[S_GW1 + j], wb = sm[S_GW1 + 128 + j], bb = sm[S_GB1 + j];
                float4 o;
                o.x = silu_(bb + y01.x * wa + y01.y * wb);
                o.y = silu_(bb + y01.z * wa + y01.w * wb);
                o.z = silu_(bb + y23.x * wa + y23.y * wb);
                o.w = silu_(bb + y23.z * wa + y23.w * wb);
                *(float4*)(sm + S_A + j * PB + pb) = o;
            }
        }
        __syncthreads();

        // GEMM 5: z2 = G1 @ gw2 + gb2 ; keep z2 in regs, write G2 = silu(z2) -> B
        float zr[16];
        {
            unsigned long long acc[8] = {};
            gemm_fwd(sm + S_A, sm + S_GW2, GWS, pg, cg, acc);
#pragma unroll
            for (int c = 0; c < 4; ++c) {
                int j = cg * 4 + c;
                float bb = sm[S_GB2 + j];
                float2 a = upk(acc[2 * c]), b = upk(acc[2 * c + 1]);
                zr[c * 4 + 0] = a.x + bb; zr[c * 4 + 1] = a.y + bb;
                zr[c * 4 + 2] = b.x + bb; zr[c * 4 + 3] = b.y + bb;
                float4 o;
                o.x = silu_(zr[c * 4 + 0]); o.y = silu_(zr[c * 4 + 1]);
                o.z = silu_(zr[c * 4 + 2]); o.w = silu_(zr[c * 4 + 3]);
                *(float4*)(sm + S_B + j * PB + pg * 4) = o;
            }
        }
        __syncthreads();

        // pass 6b+7 (tid<128): raw = G2 @ gw3 + gb3; per-path Milstein scalars
        if (tid < 128) {
            int p = tid >> 1, d = tid & 1;
            float s0 = 0.0f, s1 = 0.0f;
#pragma unroll 4
            for (int j = 0; j < HID; j += 2) {
                s0 += sm[S_B + j * PB + p] * sm[S_GW3 + j * 2 + d];
                s1 += sm[S_B + (j + 1) * PB + p] * sm[S_GW3 + (j + 1) * 2 + d];
            }
            float raw = s0 + s1 + sm[S_GB3 + d];
            float dw = sm[S_DWV + tid];
            float sp = fmaxf(raw, 0.0f) + log1pf(__expf(-fabsf(raw)));
            float g = fminf(fmaxf(sp, MIN_VOL), MAX_VOL);
            float mask = (sp > MIN_VOL && sp < MAX_VOL) ? 1.0f : 0.0f;
            float v = 0.5f * (dw * dw - dt);
            sm[S_DRW + tid] = v * g * sigm(raw) * mask;
            sm[S_GV + tid] = g;
        }
        __syncthreads();

        // pass 8: delta_z2 = dsilu(z2_reg) * (delta_raw @ gw3^T) -> B
#pragma unroll
        for (int c = 0; c < 4; ++c) {
            int j = cg * 4 + c;
            float g0 = sm[S_GW3 + j * 2], g1 = sm[S_GW3 + j * 2 + 1];
            float4 o;
            float* op = &o.x;
#pragma unroll
            for (int q = 0; q < 4; ++q) {
                int p = pg * 4 + q;
                float u = sm[S_DRW + p * 2] * g0 + sm[S_DRW + p * 2 + 1] * g1;
                op[q] = dsilu_t(zr[c * 4 + q]) * u;
            }
            *(float4*)(sm + S_B + j * PB + pg * 4) = o;
        }
        __syncthreads();

        // GEMM 9: delta_z1 = (delta_z2 @ gw2^T) * dsilu(z1 recomputed) -> A
        {
            unsigned long long acc[8] = {};
            gemm_bwd(sm + S_B, sm + S_GW2, pg, cg, acc);
#pragma unroll
            for (int c = 0; c < 4; ++c) {
                int i = cg * 4 + c;
                float w0 = sm[S_GW1 + i], w1 = sm[S_GW1 + 128 + i], bb = sm[S_GB1 + i];
                float2 a = upk(acc[2 * c]), b = upk(acc[2 * c + 1]);
                float vv[4] = {a.x, a.y, b.x, b.y};
                float4 o;
                float* op = &o.x;
#pragma unroll
                for (int q = 0; q < 4; ++q) {
                    int p = pg * 4 + q;
                    float z1 = sm[S_YSH + p * 2] * w0 + sm[S_YSH + p * 2 + 1] * w1 + bb;
                    op[q] = vv[q] * dsilu_t(z1);
                }
                *(float4*)(sm + S_A + i * PB + pg * 4) = o;
            }
        }
        __syncthreads();

        // pass 10+11 (tid<128): corr = delta_z1 @ gw1^T ; y update + output
        if (tid < 128) {
            int p = tid >> 1, d = tid & 1;
            float s0 = 0.0f, s1 = 0.0f;
#pragma unroll 4
            for (int i = 0; i < HID; i += 2) {
                s0 += sm[S_A + i * PB + p] * sm[S_GW1 + d * 128 + i];
                s1 += sm[S_A + (i + 1) * PB + p] * sm[S_GW1 + d * 128 + i + 1];
            }
            float y1 = sm[S_YSH + tid] + sm[S_FV + tid] * dt
                       + sm[S_GV + tid] * sm[S_DWV + tid] + (s0 + s1);
            sm[S_YSH + tid] = y1;
            out[(size_t)(p0 + p) * (SEQ * 2) + (size_t)(t + 1) * 2 + d] = y1;
        }
        __syncthreads();
    }
}

extern "C" void kernel_launch(void* const* d_in, const int* in_sizes, int n_in,
                              void* d_out, int out_size) {
    (void)in_sizes; (void)n_in; (void)out_size;
    cudaFuncSetAttribute(sde_kernel, cudaFuncAttributeMaxDynamicSharedMemorySize, SMEM_BYTES);
    sde_kernel<<<NBLK, NTHR, SMEM_BYTES>>>(
        (const float*)d_in[0], (const float*)d_in[1], (const float*)d_in[2],
        (const float*)d_in[3], (const float*)d_in[4], (const float*)d_in[5],
        (const float*)d_in[6], (const float*)d_in[7], (const float*)d_in[8],
        (const float*)d_in[9], (const float*)d_in[10], (const float*)d_in[11],
        (const float*)d_in[12], (const float*)d_in[13], (const float*)d_in[14],
        (float*)d_out);
}

// round 7
// speedup vs baseline: 1.1498x; 1.0322x over previous
#include <cuda_runtime.h>
#include <math.h>

#define NPATHS 8192
#define SEQ    512
#define NSTEP  511
#define HID    128
#define PB     64
#define NTHR   512
#define NBLK   (NPATHS / PB)

#define MIN_VOL 1e-4f
#define MAX_VOL 5.0f

#define GWS 132   // padded row stride for gw2

// ---- shared memory layout (floats) ----
#define S_FW1 0
#define S_FB1 384
#define S_FW2 512
#define S_FB2 16896
#define S_FW3 17024
#define S_FB3 17280
#define S_GW1 17284
#define S_GB1 17540
#define S_GW2 17668          // 132*128 = 16896
#define S_GB2 34564
#define S_GW3 34692
#define S_GB3 34948
#define S_TS  34952
#define S_A   35464          // 128*64
#define S_B   43656          // 128*64
#define S_YSH 51848
#define S_GV  51976
#define S_DWV 52104
#define S_DRW 52232
#define S_FVP 52360          // 2*128 f-GEMV partials
#define S_P   52616          // 4*128 GEMV partials
#define S_TOT 53128
#define SMEM_BYTES (S_TOT * 4)

// ---- packed f32x2 helpers ----
__device__ __forceinline__ void ffma2(unsigned long long& d, unsigned long long a, unsigned long long b) {
    asm("fma.rn.f32x2 %0, %1, %2, %0;" : "+l"(d) : "l"(a), "l"(b));
}
__device__ __forceinline__ unsigned long long dup2(float w) {
    unsigned long long r;
    asm("mov.b64 %0, {%1, %1};" : "=l"(r) : "f"(w));
    return r;
}
__device__ __forceinline__ float2 upk(unsigned long long u) {
    float2 v;
    asm("mov.b64 {%0, %1}, %2;" : "=f"(v.x), "=f"(v.y) : "l"(u));
    return v;
}

// exp-based sigmoid (accurate; forward path)
__device__ __forceinline__ float sigm(float z) {
    return __fdividef(1.0f, 1.0f + __expf(-z));
}
__device__ __forceinline__ float silu_(float z) { return z * sigm(z); }

// tanh-based sigmoid (Milstein-correction dsilu factors only)
__device__ __forceinline__ float sigm_t(float z) {
    float th;
    asm("tanh.approx.f32 %0, %1;" : "=f"(th) : "f"(0.5f * z));
    return 0.5f * th + 0.5f;
}
__device__ __forceinline__ float dsilu_t(float z) {
    float s = sigm_t(z);
    return s * (1.0f + z * (1.0f - s));
}

// forward GEMM: acc[p][j] += sum_k A[k][p] * W[k][j]
// thread tile 4 paths x 4 cols; warp tile 32 paths x 16 cols
__device__ __forceinline__ void gemm_fwd(const float* __restrict__ sA,
                                         const float* __restrict__ sW, int ws,
                                         int pg, int cg, unsigned long long acc[8]) {
#pragma unroll 2
    for (int k4 = 0; k4 < HID; k4 += 4) {
        ulonglong2 h[4];
#pragma unroll
        for (int u = 0; u < 4; ++u)
            h[u] = *(const ulonglong2*)(sA + (k4 + u) * PB + pg * 4);
#pragma unroll
        for (int u = 0; u < 4; ++u) {
            float4 w = *(const float4*)(sW + (k4 + u) * ws + cg * 4);
            unsigned long long w0 = dup2(w.x), w1 = dup2(w.y), w2 = dup2(w.z), w3 = dup2(w.w);
            ffma2(acc[0], h[u].x, w0); ffma2(acc[1], h[u].y, w0);
            ffma2(acc[2], h[u].x, w1); ffma2(acc[3], h[u].y, w1);
            ffma2(acc[4], h[u].x, w2); ffma2(acc[5], h[u].y, w2);
            ffma2(acc[6], h[u].x, w3); ffma2(acc[7], h[u].y, w3);
        }
    }
}

// backward GEMM: acc[p][i] += sum_k B[k][p] * W[i][k]
__device__ __forceinline__ void gemm_bwd(const float* __restrict__ sB,
                                         const float* __restrict__ sW,
                                         int pg, int cg, unsigned long long acc[8]) {
#pragma unroll 2
    for (int k4 = 0; k4 < HID; k4 += 4) {
        ulonglong2 h[4];
#pragma unroll
        for (int u = 0; u < 4; ++u)
            h[u] = *(const ulonglong2*)(sB + (k4 + u) * PB + pg * 4);
#pragma unroll
        for (int c = 0; c < 4; ++c) {
            float4 w = *(const float4*)(sW + (cg * 4 + c) * GWS + k4);
            unsigned long long wd;
            wd = dup2(w.x); ffma2(acc[2 * c], h[0].x, wd); ffma2(acc[2 * c + 1], h[0].y, wd);
            wd = dup2(w.y); ffma2(acc[2 * c], h[1].x, wd); ffma2(acc[2 * c + 1], h[1].y, wd);
            wd = dup2(w.z); ffma2(acc[2 * c], h[2].x, wd); ffma2(acc[2 * c + 1], h[2].y, wd);
            wd = dup2(w.w); ffma2(acc[2 * c], h[3].x, wd); ffma2(acc[2 * c + 1], h[3].y, wd);
        }
    }
}

__global__ void __launch_bounds__(NTHR, 1) sde_kernel(
    const float* __restrict__ y0, const float* __restrict__ ts, const float* __restrict__ dW,
    const float* __restrict__ fw1, const float* __restrict__ fb1,
    const float* __restrict__ fw2, const float* __restrict__ fb2,
    const float* __restrict__ fw3, const float* __restrict__ fb3,
    const float* __restrict__ gw1, const float* __restrict__ gb1,
    const float* __restrict__ gw2, const float* __restrict__ gb2,
    const float* __restrict__ gw3, const float* __restrict__ gb3,
    float* __restrict__ out) {
    extern __shared__ float sm[];
    const int tid = threadIdx.x;
    const int p0 = blockIdx.x * PB;

    {
        auto cp = [&](int dst, const float* src, int n) {
            for (int i = tid; i < n; i += NTHR) sm[dst + i] = src[i];
        };
        cp(S_FW1, fw1, 384);   cp(S_FB1, fb1, 128);
        cp(S_FW2, fw2, 16384); cp(S_FB2, fb2, 128);
        cp(S_FW3, fw3, 256);   cp(S_FB3, fb3, 2);
        cp(S_GW1, gw1, 256);   cp(S_GB1, gb1, 128);
        cp(S_GB2, gb2, 128);
        cp(S_GW3, gw3, 256);   cp(S_GB3, gb3, 2);
        cp(S_TS, ts, SEQ);
        for (int i = tid; i < 16384; i += NTHR)
            sm[S_GW2 + (i >> 7) * GWS + (i & 127)] = gw2[i];
    }
    if (tid < PB * 2) {
        float v = y0[p0 * 2 + tid];
        sm[S_YSH + tid] = v;
        out[(size_t)(p0 + (tid >> 1)) * (SEQ * 2) + (tid & 1)] = v;
    }
    __syncthreads();

    const int lane = tid & 31, wid = tid >> 5;
    const int pg = ((wid & 1) << 3) | (lane & 7);     // 0..15 (4 paths each)
    const int cg = ((wid >> 1) << 2) | (lane >> 3);   // 0..31 (4 cols each)
    const int gout = tid & 127;                        // GEMV output id
    const int gq = tid >> 7;                           // GEMV quarter
    const int gp = gout >> 1, gd = gout & 1;

    for (int t = 0; t < NSTEP; ++t) {
        const float dt = sm[S_TS + t + 1] - sm[S_TS + t];
        const float sqdt = sqrtf(dt);

        // dW prefetch + pass1: H1 = silu([y,spread]@fw1+fb1) -> A
        if (tid < PB * 2)
            sm[S_DWV + tid] = dW[(size_t)t * (NPATHS * 2) + p0 * 2 + tid] * sqdt;
#pragma unroll
        for (int it = 0; it < 4; ++it) {
            int i4 = tid + it * NTHR;
            int j = i4 >> 4, pb = (i4 & 15) * 4;
            float4 y01 = *(const float4*)(sm + S_YSH + pb * 2);
            float4 y23 = *(const float4*)(sm + S_YSH + pb * 2 + 4);
            float wa = sm[S_FW1 + j], wb = sm[S_FW1 + 128 + j], ws = sm[S_FW1 + 256 + j];
            float bb = sm[S_FB1 + j];
            float4 o;
            o.x = silu_(bb + y01.x * wa + y01.y * wb + (y01.x - y01.y) * ws);
            o.y = silu_(bb + y01.z * wa + y01.w * wb + (y01.z - y01.w) * ws);
            o.z = silu_(bb + y23.x * wa + y23.y * wb + (y23.x - y23.y) * ws);
            o.w = silu_(bb + y23.z * wa + y23.w * wb + (y23.z - y23.w) * ws);
            *(float4*)(sm + S_A + j * PB + pb) = o;
        }
        __syncthreads();

        // GEMM 2: H2 = silu(H1 @ fw2 + fb2) -> B
        {
            unsigned long long acc[8] = {};
            gemm_fwd(sm + S_A, sm + S_FW2, HID, pg, cg, acc);
#pragma unroll
            for (int c = 0; c < 4; ++c) {
                int j = cg * 4 + c;
                float bb = sm[S_FB2 + j];
                float2 a = upk(acc[2 * c]), b = upk(acc[2 * c + 1]);
                float4 o;
                o.x = silu_(a.x + bb); o.y = silu_(a.y + bb);
                o.z = silu_(b.x + bb); o.w = silu_(b.y + bb);
                *(float4*)(sm + S_B + j * PB + pg * 4) = o;
            }
        }
        __syncthreads();

        // tid<256: f-GEMV halves -> S_FVP  |  tid>=256: G1 = silu(y@gw1+gb1) -> A
        if (tid < 256) {
            int half = tid >> 7;
            int jb = half * 64;
            float s0 = 0.0f, s1 = 0.0f;
#pragma unroll 4
            for (int j = 0; j < 64; j += 2) {
                s0 += sm[S_B + (jb + j) * PB + gp] * sm[S_FW3 + (jb + j) * 2 + gd];
                s1 += sm[S_B + (jb + j + 1) * PB + gp] * sm[S_FW3 + (jb + j + 1) * 2 + gd];
            }
            sm[S_FVP + half * 128 + gout] = s0 + s1;
        } else {
#pragma unroll
            for (int it = 0; it < 8; ++it) {
                int i4 = (tid - 256) + it * 256;
                int j = i4 >> 4, pb = (i4 & 15) * 4;
                float4 y01 = *(const float4*)(sm + S_YSH + pb * 2);
                float4 y23 = *(const float4*)(sm + S_YSH + pb * 2 + 4);
                float wa = sm[S_GW1 + j], wb = sm[S_GW1 + 128 + j], bb = sm[S_GB1 + j];
                float4 o;
                o.x = silu_(bb + y01.x * wa + y01.y * wb);
                o.y = silu_(bb + y01.z * wa + y01.w * wb);
                o.z = silu_(bb + y23.x * wa + y23.y * wb);
                o.w = silu_(bb + y23.z * wa + y23.w * wb);
                *(float4*)(sm + S_A + j * PB + pb) = o;
            }
        }
        __syncthreads();

        // GEMM 5: z2 = G1 @ gw2 + gb2 ; z2 kept in regs, B = silu(z2)
        float zr[16];
        {
            unsigned long long acc[8] = {};
            gemm_fwd(sm + S_A, sm + S_GW2, GWS, pg, cg, acc);
#pragma unroll
            for (int c = 0; c < 4; ++c) {
                int j = cg * 4 + c;
                float bb = sm[S_GB2 + j];
                float2 a = upk(acc[2 * c]), b = upk(acc[2 * c + 1]);
                zr[c * 4 + 0] = a.x + bb; zr[c * 4 + 1] = a.y + bb;
                zr[c * 4 + 2] = b.x + bb; zr[c * 4 + 3] = b.y + bb;
                float4 o;
                o.x = silu_(zr[c * 4 + 0]); o.y = silu_(zr[c * 4 + 1]);
                o.z = silu_(zr[c * 4 + 2]); o.w = silu_(zr[c * 4 + 3]);
                *(float4*)(sm + S_B + j * PB + pg * 4) = o;
            }
        }
        __syncthreads();

        // raw-GEMV partials: all 512 threads, quarter each
        {
            int jb = gq * 32;
            float s0 = 0.0f, s1 = 0.0f;
#pragma unroll 4
            for (int j = 0; j < 32; j += 2) {
                s0 += sm[S_B + (jb + j) * PB + gp] * sm[S_GW3 + (jb + j) * 2 + gd];
                s1 += sm[S_B + (jb + j + 1) * PB + gp] * sm[S_GW3 + (jb + j + 1) * 2 + gd];
            }
            sm[S_P + gq * 128 + gout] = s0 + s1;
        }
        __syncthreads();

        // Milstein per-path scalars (tid < 128)
        if (tid < 128) {
            float raw = sm[S_P + tid] + sm[S_P + 128 + tid]
                      + sm[S_P + 256 + tid] + sm[S_P + 384 + tid] + sm[S_GB3 + (tid & 1)];
            float dw = sm[S_DWV + tid];
            float sp = fmaxf(raw, 0.0f) + log1pf(__expf(-fabsf(raw)));
            float g = fminf(fmaxf(sp, MIN_VOL), MAX_VOL);
            float mask = (sp > MIN_VOL && sp < MAX_VOL) ? 1.0f : 0.0f;
            float v = 0.5f * (dw * dw - dt);
            sm[S_DRW + tid] = v * g * sigm(raw) * mask;
            sm[S_GV + tid] = g;
        }
        __syncthreads();

        // pass8: delta_z2 = dsilu(z2_reg) * (delta_raw @ gw3^T) -> B
#pragma unroll
        for (int c = 0; c < 4; ++c) {
            int j = cg * 4 + c;
            float g0 = sm[S_GW3 + j * 2], g1 = sm[S_GW3 + j * 2 + 1];
            float4 o;
            float* op = &o.x;
#pragma unroll
            for (int q = 0; q < 4; ++q) {
                int p = pg * 4 + q;
                float u = sm[S_DRW + p * 2] * g0 + sm[S_DRW + p * 2 + 1] * g1;
                op[q] = dsilu_t(zr[c * 4 + q]) * u;
            }
            *(float4*)(sm + S_B + j * PB + pg * 4) = o;
        }
        __syncthreads();

        // GEMM 9: delta_z1 = (delta_z2 @ gw2^T) * dsilu(z1) -> A
        {
            unsigned long long acc[8] = {};
            gemm_bwd(sm + S_B, sm + S_GW2, pg, cg, acc);
#pragma unroll
            for (int c = 0; c < 4; ++c) {
                int i = cg * 4 + c;
                float w0 = sm[S_GW1 + i], w1 = sm[S_GW1 + 128 + i], bb = sm[S_GB1 + i];
                float2 a = upk(acc[2 * c]), b = upk(acc[2 * c + 1]);
                float vv[4] = {a.x, a.y, b.x, b.y};
                float4 o;
                float* op = &o.x;
#pragma unroll
                for (int q = 0; q < 4; ++q) {
                    int p = pg * 4 + q;
                    float z1 = sm[S_YSH + p * 2] * w0 + sm[S_YSH + p * 2 + 1] * w1 + bb;
                    op[q] = vv[q] * dsilu_t(z1);
                }
                *(float4*)(sm + S_A + i * PB + pg * 4) = o;
            }
        }
        __syncthreads();

        // corr-GEMV partials: all 512 threads
        {
            int ib = gq * 32;
            float s0 = 0.0f, s1 = 0.0f;
#pragma unroll 4
            for (int i = 0; i < 32; i += 2) {
                s0 += sm[S_A + (ib + i) * PB + gp] * sm[S_GW1 + gd * 128 + ib + i];
                s1 += sm[S_A + (ib + i + 1) * PB + gp] * sm[S_GW1 + gd * 128 + ib + i + 1];
            }
            sm[S_P + gq * 128 + gout] = s0 + s1;
        }
        __syncthreads();

        // y update + output (tid < 128)
        if (tid < 128) {
            float corr = sm[S_P + tid] + sm[S_P + 128 + tid]
                       + sm[S_P + 256 + tid] + sm[S_P + 384 + tid];
            float fv = sm[S_FVP + tid] + sm[S_FVP + 128 + tid] + sm[S_FB3 + (tid & 1)];
            float y1 = sm[S_YSH + tid] + fv * dt
                     + sm[S_GV + tid] * sm[S_DWV + tid] + corr;
            sm[S_YSH + tid] = y1;
            out[(size_t)(p0 + (tid >> 1)) * (SEQ * 2) + (size_t)(t + 1) * 2 + (tid & 1)] = y1;
        }
        __syncthreads();
    }
}

extern "C" void kernel_launch(void* const* d_in, const int* in_sizes, int n_in,
                              void* d_out, int out_size) {
    (void)in_sizes; (void)n_in; (void)out_size;
    cudaFuncSetAttribute(sde_kernel, cudaFuncAttributeMaxDynamicSharedMemorySize, SMEM_BYTES);
    sde_kernel<<<NBLK, NTHR, SMEM_BYTES>>>(
        (const float*)d_in[0], (const float*)d_in[1], (const float*)d_in[2],
        (const float*)d_in[3], (const float*)d_in[4], (const float*)d_in[5],
        (const float*)d_in[6], (const float*)d_in[7], (const float*)d_in[8],
        (const float*)d_in[9], (const float*)d_in[10], (const float*)d_in[11],
        (const float*)d_in[12], (const float*)d_in[13], (const float*)d_in[14],
        (float*)d_out);
}

// round 8
// speedup vs baseline: 1.2320x; 1.0715x over previous
#include <cuda_runtime.h>
#include <math.h>

#define NPATHS 8192
#define SEQ    512
#define NSTEP  511
#define HID    128
#define PB     64
#define NTHR   512
#define NBLK   (NPATHS / PB)

#define MIN_VOL 1e-4f
#define MAX_VOL 5.0f

#define GWS 132   // padded row stride for gw2

// ---- shared memory layout (floats) ----
#define S_FW1 0
#define S_FB1 384
#define S_FW2 512
#define S_FB2 16896
#define S_FW3 17024
#define S_FB3 17280
#define S_GW1 17284
#define S_GB1 17540
#define S_GW2 17668          // 132*128 = 16896
#define S_GB2 34564
#define S_GW3 34692
#define S_GB3 34948
#define S_TS  34952
#define S_A   35464          // 8192: H1
#define S_B   43656          // 8192: G1 then delta_z2
#define S_PF  51848          // 1024: f partials   (8 groups x 128)
#define S_PR  52872          // 1024: raw partials
#define S_PC  53896          // 1024: corr partials
#define S_YSH 54920
#define S_GV  55048
#define S_DWV 55176
#define S_DRW 55304
#define S_TOT 55432
#define SMEM_BYTES (S_TOT * 4)

// ---- packed f32x2 helpers ----
__device__ __forceinline__ void ffma2(unsigned long long& d, unsigned long long a, unsigned long long b) {
    asm("fma.rn.f32x2 %0, %1, %2, %0;" : "+l"(d) : "l"(a), "l"(b));
}
__device__ __forceinline__ unsigned long long dup2(float w) {
    unsigned long long r;
    asm("mov.b64 %0, {%1, %1};" : "=l"(r) : "f"(w));
    return r;
}
__device__ __forceinline__ float2 upk(unsigned long long u) {
    float2 v;
    asm("mov.b64 {%0, %1}, %2;" : "=f"(v.x), "=f"(v.y) : "l"(u));
    return v;
}

// exp-based sigmoid (accurate; forward path)
__device__ __forceinline__ float sigm(float z) {
    return __fdividef(1.0f, 1.0f + __expf(-z));
}
__device__ __forceinline__ float silu_(float z) { return z * sigm(z); }

// tanh-based sigmoid (Milstein-correction dsilu factors only)
__device__ __forceinline__ float sigm_t(float z) {
    float th;
    asm("tanh.approx.f32 %0, %1;" : "=f"(th) : "f"(0.5f * z));
    return 0.5f * th + 0.5f;
}
__device__ __forceinline__ float dsilu_t(float z) {
    float s = sigm_t(z);
    return s * (1.0f + z * (1.0f - s));
}

// forward GEMM: acc[p][j] += sum_k A[k][p] * W[k][j]
__device__ __forceinline__ void gemm_fwd(const float* __restrict__ sA,
                                         const float* __restrict__ sW, int ws,
                                         int pg, int cg, unsigned long long acc[8]) {
#pragma unroll 2
    for (int k4 = 0; k4 < HID; k4 += 4) {
        ulonglong2 h[4];
#pragma unroll
        for (int u = 0; u < 4; ++u)
            h[u] = *(const ulonglong2*)(sA + (k4 + u) * PB + pg * 4);
#pragma unroll
        for (int u = 0; u < 4; ++u) {
            float4 w = *(const float4*)(sW + (k4 + u) * ws + cg * 4);
            unsigned long long w0 = dup2(w.x), w1 = dup2(w.y), w2 = dup2(w.z), w3 = dup2(w.w);
            ffma2(acc[0], h[u].x, w0); ffma2(acc[1], h[u].y, w0);
            ffma2(acc[2], h[u].x, w1); ffma2(acc[3], h[u].y, w1);
            ffma2(acc[4], h[u].x, w2); ffma2(acc[5], h[u].y, w2);
            ffma2(acc[6], h[u].x, w3); ffma2(acc[7], h[u].y, w3);
        }
    }
}

// backward GEMM: acc[p][i] += sum_k B[k][p] * W[i][k]
__device__ __forceinline__ void gemm_bwd(const float* __restrict__ sB,
                                         const float* __restrict__ sW,
                                         int pg, int cg, unsigned long long acc[8]) {
#pragma unroll 2
    for (int k4 = 0; k4 < HID; k4 += 4) {
        ulonglong2 h[4];
#pragma unroll
        for (int u = 0; u < 4; ++u)
            h[u] = *(const ulonglong2*)(sB + (k4 + u) * PB + pg * 4);
#pragma unroll
        for (int c = 0; c < 4; ++c) {
            float4 w = *(const float4*)(sW + (cg * 4 + c) * GWS + k4);
            unsigned long long wd;
            wd = dup2(w.x); ffma2(acc[2 * c], h[0].x, wd); ffma2(acc[2 * c + 1], h[0].y, wd);
            wd = dup2(w.y); ffma2(acc[2 * c], h[1].x, wd); ffma2(acc[2 * c + 1], h[1].y, wd);
            wd = dup2(w.z); ffma2(acc[2 * c], h[2].x, wd); ffma2(acc[2 * c + 1], h[2].y, wd);
            wd = dup2(w.w); ffma2(acc[2 * c], h[3].x, wd); ffma2(acc[2 * c + 1], h[3].y, wd);
        }
    }
}

// reduce 8 partials across the 4 cg-subgroups of a warp (lane bits 3,4),
// then 8 lanes write 2x float4 into P[(wid>>1)*128 + pg*8 .. +7]
__device__ __forceinline__ void part_reduce_store(float part[8], float* __restrict__ dst,
                                                  int lane, int wid, int pg) {
#pragma unroll
    for (int v = 0; v < 8; ++v) {
        part[v] += __shfl_xor_sync(0xffffffffu, part[v], 8);
        part[v] += __shfl_xor_sync(0xffffffffu, part[v], 16);
    }
    if ((lane >> 3) == 0) {
        float4 o0 = {part[0], part[1], part[2], part[3]};
        float4 o1 = {part[4], part[5], part[6], part[7]};
        *(float4*)(dst + (wid >> 1) * 128 + pg * 8) = o0;
        *(float4*)(dst + (wid >> 1) * 128 + pg * 8 + 4) = o1;
    }
}

__global__ void __launch_bounds__(NTHR, 1) sde_kernel(
    const float* __restrict__ y0, const float* __restrict__ ts, const float* __restrict__ dW,
    const float* __restrict__ fw1, const float* __restrict__ fb1,
    const float* __restrict__ fw2, const float* __restrict__ fb2,
    const float* __restrict__ fw3, const float* __restrict__ fb3,
    const float* __restrict__ gw1, const float* __restrict__ gb1,
    const float* __restrict__ gw2, const float* __restrict__ gb2,
    const float* __restrict__ gw3, const float* __restrict__ gb3,
    float* __restrict__ out) {
    extern __shared__ float sm[];
    const int tid = threadIdx.x;
    const int p0 = blockIdx.x * PB;

    {
        auto cp = [&](int dst, const float* src, int n) {
            for (int i = tid; i < n; i += NTHR) sm[dst + i] = src[i];
        };
        cp(S_FW1, fw1, 384);   cp(S_FB1, fb1, 128);
        cp(S_FW2, fw2, 16384); cp(S_FB2, fb2, 128);
        cp(S_FW3, fw3, 256);   cp(S_FB3, fb3, 2);
        cp(S_GW1, gw1, 256);   cp(S_GB1, gb1, 128);
        cp(S_GB2, gb2, 128);
        cp(S_GW3, gw3, 256);   cp(S_GB3, gb3, 2);
        cp(S_TS, ts, SEQ);
        for (int i = tid; i < 16384; i += NTHR)
            sm[S_GW2 + (i >> 7) * GWS + (i & 127)] = gw2[i];
    }
    if (tid < PB * 2) {
        float v = y0[p0 * 2 + tid];
        sm[S_YSH + tid] = v;
        out[(size_t)(p0 + (tid >> 1)) * (SEQ * 2) + (tid & 1)] = v;
    }
    __syncthreads();

    const int lane = tid & 31, wid = tid >> 5;
    const int pg = ((wid & 1) << 3) | (lane & 7);     // 0..15 (4 paths each)
    const int cg = ((wid >> 1) << 2) | (lane >> 3);   // 0..31 (4 cols each)

    for (int t = 0; t < NSTEP; ++t) {
        const float dt = sm[S_TS + t + 1] - sm[S_TS + t];
        const float sqdt = sqrtf(dt);

        // pass1: H1 = silu([y,spread]@fw1+fb1) -> A, G1 = silu(y@gw1+gb1) -> B, dW prefetch
        if (tid < PB * 2)
            sm[S_DWV + tid] = dW[(size_t)t * (NPATHS * 2) + p0 * 2 + tid] * sqdt;
#pragma unroll
        for (int it = 0; it < 4; ++it) {
            int i4 = tid + it * NTHR;          // 2048 float4 tasks
            int j = i4 >> 4, pb = (i4 & 15) * 4;
            float4 y01 = *(const float4*)(sm + S_YSH + pb * 2);
            float4 y23 = *(const float4*)(sm + S_YSH + pb * 2 + 4);
            float fa = sm[S_FW1 + j], fb = sm[S_FW1 + 128 + j], fs = sm[S_FW1 + 256 + j];
            float fbb = sm[S_FB1 + j];
            float4 oF;
            oF.x = silu_(fbb + y01.x * fa + y01.y * fb + (y01.x - y01.y) * fs);
            oF.y = silu_(fbb + y01.z * fa + y01.w * fb + (y01.z - y01.w) * fs);
            oF.z = silu_(fbb + y23.x * fa + y23.y * fb + (y23.x - y23.y) * fs);
            oF.w = silu_(fbb + y23.z * fa + y23.w * fb + (y23.z - y23.w) * fs);
            *(float4*)(sm + S_A + j * PB + pb) = oF;
            float ga = sm[S_GW1 + j], gb = sm[S_GW1 + 128 + j], gbb = sm[S_GB1 + j];
            float4 oG;
            oG.x = silu_(gbb + y01.x * ga + y01.y * gb);
            oG.y = silu_(gbb + y01.z * ga + y01.w * gb);
            oG.z = silu_(gbb + y23.x * ga + y23.y * gb);
            oG.w = silu_(gbb + y23.z * ga + y23.w * gb);
            *(float4*)(sm + S_B + j * PB + pb) = oG;
        }
        __syncthreads();

        // GEMM2: z = H1 @ fw2 + fb2 ; f-partials = silu(z) @ fw3 -> PF  (H2 never stored)
        {
            unsigned long long acc[8] = {};
            gemm_fwd(sm + S_A, sm + S_FW2, HID, pg, cg, acc);
            float part[8] = {0, 0, 0, 0, 0, 0, 0, 0};
#pragma unroll
            for (int c = 0; c < 4; ++c) {
                int j = cg * 4 + c;
                float bb = sm[S_FB2 + j];
                float w0 = sm[S_FW3 + j * 2], w1 = sm[S_FW3 + j * 2 + 1];
                float2 a = upk(acc[2 * c]), b = upk(acc[2 * c + 1]);
                float h0 = silu_(a.x + bb), h1 = silu_(a.y + bb);
                float h2 = silu_(b.x + bb), h3 = silu_(b.y + bb);
                part[0] += h0 * w0; part[1] += h0 * w1;
                part[2] += h1 * w0; part[3] += h1 * w1;
                part[4] += h2 * w0; part[5] += h2 * w1;
                part[6] += h3 * w0; part[7] += h3 * w1;
            }
            part_reduce_store(part, sm + S_PF, lane, wid, pg);
        }

        // GEMM5 (no barrier needed — reads B only): z2 = G1 @ gw2 + gb2 (kept in regs);
        // raw-partials = silu(z2) @ gw3 -> PR  (G2 never stored)
        float zr[16];
        {
            unsigned long long acc[8] = {};
            gemm_fwd(sm + S_B, sm + S_GW2, GWS, pg, cg, acc);
            float part[8] = {0, 0, 0, 0, 0, 0, 0, 0};
#pragma unroll
            for (int c = 0; c < 4; ++c) {
                int j = cg * 4 + c;
                float bb = sm[S_GB2 + j];
                float w0 = sm[S_GW3 + j * 2], w1 = sm[S_GW3 + j * 2 + 1];
                float2 a = upk(acc[2 * c]), b = upk(acc[2 * c + 1]);
                zr[c * 4 + 0] = a.x + bb; zr[c * 4 + 1] = a.y + bb;
                zr[c * 4 + 2] = b.x + bb; zr[c * 4 + 3] = b.y + bb;
                float g0 = silu_(zr[c * 4 + 0]), g1 = silu_(zr[c * 4 + 1]);
                float g2 = silu_(zr[c * 4 + 2]), g3 = silu_(zr[c * 4 + 3]);
                part[0] += g0 * w0; part[1] += g0 * w1;
                part[2] += g1 * w0; part[3] += g1 * w1;
                part[4] += g2 * w0; part[5] += g2 * w1;
                part[6] += g3 * w0; part[7] += g3 * w1;
            }
            part_reduce_store(part, sm + S_PR, lane, wid, pg);
        }
        __syncthreads();

        // Milstein per-path scalars (tid<128): raw = sum(PR) + gb3
        if (tid < 128) {
            float raw = sm[S_GB3 + (tid & 1)];
#pragma unroll
            for (int g = 0; g < 8; ++g) raw += sm[S_PR + g * 128 + tid];
            float dw = sm[S_DWV + tid];
            float sp = fmaxf(raw, 0.0f) + log1pf(__expf(-fabsf(raw)));
            float g = fminf(fmaxf(sp, MIN_VOL), MAX_VOL);
            float mask = (sp > MIN_VOL && sp < MAX_VOL) ? 1.0f : 0.0f;
            float v = 0.5f * (dw * dw - dt);
            sm[S_DRW + tid] = v * g * sigm(raw) * mask;
            sm[S_GV + tid] = g;
        }
        __syncthreads();

        // pass8: delta_z2 = dsilu(z2_reg) * (delta_raw @ gw3^T) -> B
#pragma unroll
        for (int c = 0; c < 4; ++c) {
            int j = cg * 4 + c;
            float g0 = sm[S_GW3 + j * 2], g1 = sm[S_GW3 + j * 2 + 1];
            float4 o;
            float* op = &o.x;
#pragma unroll
            for (int q = 0; q < 4; ++q) {
                int p = pg * 4 + q;
                float u = sm[S_DRW + p * 2] * g0 + sm[S_DRW + p * 2 + 1] * g1;
                op[q] = dsilu_t(zr[c * 4 + q]) * u;
            }
            *(float4*)(sm + S_B + j * PB + pg * 4) = o;
        }
        __syncthreads();

        // GEMM9: pre = delta_z2 @ gw2^T ; dz1 = pre * dsilu(z1 recomputed);
        // corr-partials = dz1 @ gw1^T -> PC   (delta_z1 never stored)
        {
            unsigned long long acc[8] = {};
            gemm_bwd(sm + S_B, sm + S_GW2, pg, cg, acc);
            float part[8] = {0, 0, 0, 0, 0, 0, 0, 0};
#pragma unroll
            for (int c = 0; c < 4; ++c) {
                int i = cg * 4 + c;
                float w0 = sm[S_GW1 + i], w1 = sm[S_GW1 + 128 + i], bb = sm[S_GB1 + i];
                float2 a = upk(acc[2 * c]), b = upk(acc[2 * c + 1]);
                float vv[4] = {a.x, a.y, b.x, b.y};
#pragma unroll
                for (int q = 0; q < 4; ++q) {
                    int p = pg * 4 + q;
                    float z1 = sm[S_YSH + p * 2] * w0 + sm[S_YSH + p * 2 + 1] * w1 + bb;
                    float dz = vv[q] * dsilu_t(z1);
                    part[q * 2 + 0] += dz * w0;
                    part[q * 2 + 1] += dz * w1;
                }
            }
            part_reduce_store(part, sm + S_PC, lane, wid, pg);
        }
        __syncthreads();

        // final: f = sum(PF)+fb3, corr = sum(PC); y update + output (tid<128)
        if (tid < 128) {
            float fv = sm[S_FB3 + (tid & 1)], corr = 0.0f;
#pragma unroll
            for (int g = 0; g < 8; ++g) {
                fv += sm[S_PF + g * 128 + tid];
                corr += sm[S_PC + g * 128 + tid];
            }
            float y1 = sm[S_YSH + tid] + fv * dt
                     + sm[S_GV + tid] * sm[S_DWV + tid] + corr;
            sm[S_YSH + tid] = y1;
            out[(size_t)(p0 + (tid >> 1)) * (SEQ * 2) + (size_t)(t + 1) * 2 + (tid & 1)] = y1;
        }
        __syncthreads();
    }
}

extern "C" void kernel_launch(void* const* d_in, const int* in_sizes, int n_in,
                              void* d_out, int out_size) {
    (void)in_sizes; (void)n_in; (void)out_size;
    cudaFuncSetAttribute(sde_kernel, cudaFuncAttributeMaxDynamicSharedMemorySize, SMEM_BYTES);
    sde_kernel<<<NBLK, NTHR, SMEM_BYTES>>>(
        (const float*)d_in[0], (const float*)d_in[1], (const float*)d_in[2],
        (const float*)d_in[3], (const float*)d_in[4], (const float*)d_in[5],
        (const float*)d_in[6], (const float*)d_in[7], (const float*)d_in[8],
        (const float*)d_in[9], (const float*)d_in[10], (const float*)d_in[11],
        (const float*)d_in[12], (const float*)d_in[13], (const float*)d_in[14],
        (float*)d_out);
}